// round 1
// baseline (speedup 1.0000x reference)
#include <cuda_runtime.h>

#define NB 4
#define NS 2048
#define ND 1024
#define NH 16
#define DH 64
#define N3 3072

// 32MB scratch for Q in [B,H,S,Dh] layout (device global: allocation-free)
__device__ float g_qbuf[(size_t)NB * NH * NS * DH];

// ---------------------------------------------------------------------------
// QKV GEMM: C[8192,3072] = A[8192,1024] @ W[1024,3072] + bias
// BM=128, BN=64, BK=16, 256 threads, 8x4 per-thread tile.
// Fused epilogue scatters to [B,H,S,Dh]: Q -> g_qbuf, K/V -> present region.
// ---------------------------------------------------------------------------
__global__ __launch_bounds__(256) void qkv_gemm_kernel(
    const float* __restrict__ A, const float* __restrict__ W,
    const float* __restrict__ bias,
    float* __restrict__ kout, float* __restrict__ vout)
{
    __shared__ float As[16][128];
    __shared__ float Bs[16][68];
    const int tid = threadIdx.x;
    const int ty = tid >> 4, tx = tid & 15;
    const int row0 = blockIdx.y * 128;
    const int col0 = blockIdx.x * 64;

    float acc[8][4];
#pragma unroll
    for (int i = 0; i < 8; i++)
#pragma unroll
        for (int j = 0; j < 4; j++) acc[i][j] = 0.0f;

    for (int kt = 0; kt < ND / 16; kt++) {
        // A tile 128x16 -> As[k][m] (transposed for broadcast reads)
#pragma unroll
        for (int f0 = 0; f0 < 2; f0++) {
            int f = tid + f0 * 256;              // 512 float4s
            int r = f >> 2, c4 = (f & 3) * 4;
            float4 v = *(const float4*)&A[(size_t)(row0 + r) * ND + kt * 16 + c4];
            As[c4 + 0][r] = v.x; As[c4 + 1][r] = v.y;
            As[c4 + 2][r] = v.z; As[c4 + 3][r] = v.w;
        }
        // B tile 16x64
        {
            int r = tid >> 4, c4 = (tid & 15) * 4;
            *(float4*)&Bs[r][c4] =
                *(const float4*)&W[(size_t)(kt * 16 + r) * N3 + col0 + c4];
        }
        __syncthreads();
#pragma unroll
        for (int kk = 0; kk < 16; kk++) {
            float4 a0 = *(const float4*)&As[kk][ty * 8];
            float4 a1 = *(const float4*)&As[kk][ty * 8 + 4];
            float4 b4 = *(const float4*)&Bs[kk][tx * 4];
            float a[8] = {a0.x, a0.y, a0.z, a0.w, a1.x, a1.y, a1.z, a1.w};
            float b[4] = {b4.x, b4.y, b4.z, b4.w};
#pragma unroll
            for (int i = 0; i < 8; i++)
#pragma unroll
                for (int j = 0; j < 4; j++)
                    acc[i][j] = fmaf(a[i], b[j], acc[i][j]);
        }
        __syncthreads();
    }

    // Epilogue: bias + scatter. col0 is a multiple of 64 so (sel, head) are
    // constant per block and d = tx*4+j.
    const int n0 = col0 + tx * 4;
    float4 bv = *(const float4*)&bias[n0];
    const int sel = col0 / ND;
    const int h = (col0 % ND) / DH;
    float* dst = (sel == 0) ? g_qbuf : ((sel == 1) ? kout : vout);
#pragma unroll
    for (int i = 0; i < 8; i++) {
        int m = row0 + ty * 8 + i;
        int b = m / NS, s = m % NS;
        float4 r4;
        r4.x = acc[i][0] + bv.x; r4.y = acc[i][1] + bv.y;
        r4.z = acc[i][2] + bv.z; r4.w = acc[i][3] + bv.w;
        size_t idx = ((((size_t)b * NH + h) * NS + s) * DH) + tx * 4;
        *(float4*)&dst[idx] = r4;
    }
}

// ---------------------------------------------------------------------------
// Flash attention: Bq=Bk=64, 128 threads, 8x4 per-thread tiles for QK^T and PV,
// online softmax, causal tile skipping. K/V read from the present output.
// ---------------------------------------------------------------------------
__global__ __launch_bounds__(128) void attn_kernel(
    const float* __restrict__ mask,
    float* __restrict__ out,
    const float* __restrict__ kb, const float* __restrict__ vb)
{
    extern __shared__ float sm[];
    float* Qs   = sm;              // 64*64
    float* Ks   = Qs + 64 * 64;    // 64*68
    float* Vs   = Ks + 64 * 68;    // 64*68
    float* Ps   = Vs + 64 * 68;    // 64*68
    float* addm = Ps + 64 * 68;    // 64

    const int tid = threadIdx.x;
    const int ty = tid >> 4, tx = tid & 15;
    const int qi = blockIdx.x, h = blockIdx.y, b = blockIdx.z;
    const int q0 = qi * 64;
    const size_t head_off = (((size_t)b * NH + h) * NS) * DH;
    const float* Qg = g_qbuf + head_off;
    const float* Kg = kb + head_off;
    const float* Vg = vb + head_off;

    // Load Q tile once
#pragma unroll
    for (int f0 = 0; f0 < 8; f0++) {
        int f = tid + f0 * 128;
        int r = f >> 4, c4 = (f & 15) * 4;
        *(float4*)&Qs[r * 64 + c4] =
            *(const float4*)&Qg[(size_t)(q0 + r) * DH + c4];
    }

    float o[8][4];
    float mr[8], lr[8];
#pragma unroll
    for (int i = 0; i < 8; i++) {
        mr[i] = -1e30f; lr[i] = 0.0f;
#pragma unroll
        for (int j = 0; j < 4; j++) o[i][j] = 0.0f;
    }
    const float scale = 0.125f;  // 1/sqrt(64)

    for (int kt = 0; kt <= qi; kt++) {
        const int k0 = kt * 64;
        __syncthreads();  // protect Ks/Vs/Ps reuse across iterations (and Qs on iter 0)
#pragma unroll
        for (int f0 = 0; f0 < 8; f0++) {
            int f = tid + f0 * 128;
            int r = f >> 4, c4 = (f & 15) * 4;
            *(float4*)&Ks[r * 68 + c4] =
                *(const float4*)&Kg[(size_t)(k0 + r) * DH + c4];
            *(float4*)&Vs[r * 68 + c4] =
                *(const float4*)&Vg[(size_t)(k0 + r) * DH + c4];
        }
        if (tid < 64)
            addm[tid] = (1.0f - mask[(size_t)b * NS + k0 + tid]) * (-10000.0f);
        __syncthreads();

        // S = Q @ K^T  (64x64x64)
        float s[8][4];
#pragma unroll
        for (int i = 0; i < 8; i++)
#pragma unroll
            for (int j = 0; j < 4; j++) s[i][j] = 0.0f;

#pragma unroll
        for (int d = 0; d < 64; d += 4) {
            float4 k4[4];
#pragma unroll
            for (int j = 0; j < 4; j++)
                k4[j] = *(const float4*)&Ks[(tx * 4 + j) * 68 + d];
#pragma unroll
            for (int i = 0; i < 8; i++) {
                float4 a4 = *(const float4*)&Qs[(ty * 8 + i) * 64 + d];
#pragma unroll
                for (int j = 0; j < 4; j++) {
                    s[i][j] = fmaf(a4.x, k4[j].x, s[i][j]);
                    s[i][j] = fmaf(a4.y, k4[j].y, s[i][j]);
                    s[i][j] = fmaf(a4.z, k4[j].z, s[i][j]);
                    s[i][j] = fmaf(a4.w, k4[j].w, s[i][j]);
                }
            }
        }

        float am[4];
#pragma unroll
        for (int j = 0; j < 4; j++) am[j] = addm[tx * 4 + j];
        const bool diag = (kt == qi);

        // online softmax (row reductions across the 16 tx lanes)
#pragma unroll
        for (int i = 0; i < 8; i++) {
            int r = q0 + ty * 8 + i;
            float mx = -1e30f;
#pragma unroll
            for (int j = 0; j < 4; j++) {
                float v = fmaf(s[i][j], scale, am[j]);
                if (diag && (k0 + tx * 4 + j > r)) v = -1e30f;
                s[i][j] = v;
                mx = fmaxf(mx, v);
            }
#pragma unroll
            for (int off = 8; off > 0; off >>= 1)
                mx = fmaxf(mx, __shfl_xor_sync(0xffffffffu, mx, off));
            float mn = fmaxf(mr[i], mx);
            float alpha = __expf(mr[i] - mn);
            mr[i] = mn;
            float ps = 0.0f;
#pragma unroll
            for (int j = 0; j < 4; j++) {
                float p = __expf(s[i][j] - mn);
                s[i][j] = p;
                ps += p;
            }
#pragma unroll
            for (int off = 8; off > 0; off >>= 1)
                ps += __shfl_xor_sync(0xffffffffu, ps, off);
            lr[i] = lr[i] * alpha + ps;
#pragma unroll
            for (int j = 0; j < 4; j++) o[i][j] *= alpha;
        }

        // stage P
#pragma unroll
        for (int i = 0; i < 8; i++) {
            float4 p4 = make_float4(s[i][0], s[i][1], s[i][2], s[i][3]);
            *(float4*)&Ps[(ty * 8 + i) * 68 + tx * 4] = p4;
        }
        __syncthreads();

        // O += P @ V  (64x64x64)
#pragma unroll
        for (int c = 0; c < 64; c += 4) {
            float4 v4[4];
#pragma unroll
            for (int cc = 0; cc < 4; cc++)
                v4[cc] = *(const float4*)&Vs[(c + cc) * 68 + tx * 4];
#pragma unroll
            for (int i = 0; i < 8; i++) {
                float4 p4 = *(const float4*)&Ps[(ty * 8 + i) * 68 + c];
                float pc[4] = {p4.x, p4.y, p4.z, p4.w};
#pragma unroll
                for (int cc = 0; cc < 4; cc++) {
                    o[i][0] = fmaf(pc[cc], v4[cc].x, o[i][0]);
                    o[i][1] = fmaf(pc[cc], v4[cc].y, o[i][1]);
                    o[i][2] = fmaf(pc[cc], v4[cc].z, o[i][2]);
                    o[i][3] = fmaf(pc[cc], v4[cc].w, o[i][3]);
                }
            }
        }
    }

    // epilogue: normalize + merge heads -> out[B,S,D]
#pragma unroll
    for (int i = 0; i < 8; i++) {
        float inv = 1.0f / lr[i];
        int r = q0 + ty * 8 + i;
        float4 r4 = make_float4(o[i][0] * inv, o[i][1] * inv,
                                o[i][2] * inv, o[i][3] * inv);
        *(float4*)&out[((size_t)b * NS + r) * ND + h * DH + tx * 4] = r4;
    }
}

extern "C" void kernel_launch(void* const* d_in, const int* in_sizes, int n_in,
                              void* d_out, int out_size) {
    const float* hs   = (const float*)d_in[0];  // [B,S,D]
    const float* mask = (const float*)d_in[1];  // [B,S]
    const float* w    = (const float*)d_in[2];  // [D,3D]
    const float* bias = (const float*)d_in[3];  // [3D]

    float* out = (float*)d_out;
    // layout: attn_output [B,S,D] ++ present [2,B,H,S,Dh]
    float* kout = out + (size_t)NB * NS * ND;              // present[0] = K
    float* vout = kout + (size_t)NB * NH * NS * DH;        // present[1] = V

    static bool attr_set = false;
    if (!attr_set) {
        cudaFuncSetAttribute(attn_kernel,
                             cudaFuncAttributeMaxDynamicSharedMemorySize,
                             (int)((4096 + 3 * 64 * 68 + 64) * sizeof(float)));
        attr_set = true;
    }

    dim3 g1(N3 / 64, (NB * NS) / 128);
    qkv_gemm_kernel<<<g1, 256>>>(hs, w, bias, kout, vout);

    size_t smem = (4096 + 3 * 64 * 68 + 64) * sizeof(float);
    dim3 g2(NS / 64, NH, NB);
    attn_kernel<<<g2, 128, smem>>>(mask, out, kout, vout);
}

// round 3
// speedup vs baseline: 1.1467x; 1.1467x over previous
#include <cuda_runtime.h>
#include <cstdint>

#define NB 4
#define NS 2048
#define ND 1024
#define NH 16
#define DH 64
#define N3 3072
#define MROWS (NB * NS)  // 8192

// Device scratch (allocation-free)
__device__ float g_qbuf[(size_t)NB * NH * NS * DH];  // Q in [B,H,S,Dh]
__device__ float g_wt[(size_t)N3 * ND];              // W^T [3072,1024]

// packed fp32x2 FMA: c.lo += a.lo*b.lo; c.hi += a.hi*b.hi  (exact fp32 FMAs)
#define FMA2(c, a, b) \
    asm("fma.rn.f32x2 %0, %1, %2, %0;" : "+l"(c) : "l"(a), "l"(b))

__device__ __forceinline__ float hadd2(unsigned long long v) {
    float lo, hi;
    asm("mov.b64 {%0, %1}, %2;" : "=f"(lo), "=f"(hi) : "l"(v));
    return lo + hi;
}

// ---------------------------------------------------------------------------
// Prekernel: transpose W [1024,3072] -> Wt [3072,1024]
// ---------------------------------------------------------------------------
__global__ __launch_bounds__(256) void wt_kernel(const float* __restrict__ W) {
    __shared__ float t[32][33];
    const int n0 = blockIdx.x * 32, k0 = blockIdx.y * 32;
    const int tx = threadIdx.x, ty = threadIdx.y;  // 32 x 8
#pragma unroll
    for (int j = 0; j < 4; j++)
        t[ty + j * 8][tx] = W[(size_t)(k0 + ty + j * 8) * N3 + n0 + tx];
    __syncthreads();
#pragma unroll
    for (int j = 0; j < 4; j++)
        g_wt[(size_t)(n0 + ty + j * 8) * ND + k0 + tx] = t[tx][ty + j * 8];
}

// ---------------------------------------------------------------------------
// QKV GEMM: C[8192,3072] = A @ W + bias, f32x2-packed over k.
// BM=BN=128, BK=16, 256 threads, 8x8 per thread (rows ty+16i, cols tx+16j).
// Fused epilogue scatters Q->g_qbuf, K/V->present.
// ---------------------------------------------------------------------------
#define AST 20
#define NKT (ND / 16)

__global__ __launch_bounds__(256) void qkv_gemm2(
    const float* __restrict__ A, const float* __restrict__ bias,
    float* __restrict__ kout, float* __restrict__ vout)
{
    __shared__ float As[2][128 * AST];
    __shared__ float Bs[2][128 * AST];
    __shared__ float sb[128];

    const int tid = threadIdx.x;
    const int ty = tid >> 4, tx = tid & 15;
    const int m0 = blockIdx.y * 128;
    const int n0 = blockIdx.x * 128;

    const int lr = tid >> 2;             // 0..63
    const int lc = (tid & 3) * 4;        // k offset within tile

    if (tid < 128) sb[tid] = bias[n0 + tid];

    unsigned long long acc[8][8];
#pragma unroll
    for (int i = 0; i < 8; i++)
#pragma unroll
        for (int j = 0; j < 8; j++) acc[i][j] = 0ULL;

    const float* Bt = g_wt + (size_t)n0 * ND;

    // stage 0
    {
        float4 a0 = *(const float4*)&A[(size_t)(m0 + lr) * ND + lc];
        float4 a1 = *(const float4*)&A[(size_t)(m0 + lr + 64) * ND + lc];
        float4 b0 = *(const float4*)&Bt[(size_t)lr * ND + lc];
        float4 b1 = *(const float4*)&Bt[(size_t)(lr + 64) * ND + lc];
        *(float4*)&As[0][lr * AST + lc] = a0;
        *(float4*)&As[0][(lr + 64) * AST + lc] = a1;
        *(float4*)&Bs[0][lr * AST + lc] = b0;
        *(float4*)&Bs[0][(lr + 64) * AST + lc] = b1;
    }
    __syncthreads();

    for (int kt = 0; kt < NKT; kt++) {
        const int buf = kt & 1;
        float4 a0, a1, b0, b1;
        const bool more = (kt + 1 < NKT);
        if (more) {
            const int kg = (kt + 1) * 16 + lc;
            a0 = *(const float4*)&A[(size_t)(m0 + lr) * ND + kg];
            a1 = *(const float4*)&A[(size_t)(m0 + lr + 64) * ND + kg];
            b0 = *(const float4*)&Bt[(size_t)lr * ND + kg];
            b1 = *(const float4*)&Bt[(size_t)(lr + 64) * ND + kg];
        }
#pragma unroll
        for (int k4 = 0; k4 < 4; k4++) {
            unsigned long long a2[8][2], b2[8][2];
#pragma unroll
            for (int i = 0; i < 8; i++) {
                ulonglong2 t = *(const ulonglong2*)&As[buf][(ty + 16 * i) * AST + k4 * 4];
                a2[i][0] = t.x; a2[i][1] = t.y;
            }
#pragma unroll
            for (int j = 0; j < 8; j++) {
                ulonglong2 t = *(const ulonglong2*)&Bs[buf][(tx + 16 * j) * AST + k4 * 4];
                b2[j][0] = t.x; b2[j][1] = t.y;
            }
#pragma unroll
            for (int i = 0; i < 8; i++)
#pragma unroll
                for (int j = 0; j < 8; j++) {
                    FMA2(acc[i][j], a2[i][0], b2[j][0]);
                    FMA2(acc[i][j], a2[i][1], b2[j][1]);
                }
        }
        if (more) {
            const int nb = 1 - buf;
            *(float4*)&As[nb][lr * AST + lc] = a0;
            *(float4*)&As[nb][(lr + 64) * AST + lc] = a1;
            *(float4*)&Bs[nb][lr * AST + lc] = b0;
            *(float4*)&Bs[nb][(lr + 64) * AST + lc] = b1;
        }
        __syncthreads();
    }

    // Epilogue: horizontal add + bias + head-split scatter.
    const int sel = n0 / ND;  // tile fully inside one of Q/K/V (128 | 1024)
    float* dst = (sel == 0) ? g_qbuf : ((sel == 1) ? kout : vout);
#pragma unroll
    for (int i = 0; i < 8; i++) {
        const int m = m0 + ty + 16 * i;
        const int b = m >> 11, s = m & (NS - 1);
        const size_t row = ((size_t)b * NH) * NS;  // partial
#pragma unroll
        for (int j = 0; j < 8; j++) {
            const int n = tx + 16 * j;               // 0..127
            const int ng = n0 + n;
            const int h = (ng & (ND - 1)) >> 6;
            const int d = ng & 63;
            dst[((row + (size_t)h * NS + s) * DH) + d] = hadd2(acc[i][j]) + sb[n];
        }
    }
}

// ---------------------------------------------------------------------------
// Flash attention, f32x2-packed. Bq=64, Bk=128, 128 threads.
// QK^T: 8x8/thread packed over d. PV: 8x4/thread packed over k (V transposed
// in smem). P aliases K's smem. Online softmax.
// smem floats: Qs[64*68]=4352, Ks[128*68]=8704 (aliased by Ps[64*132]=8448),
//              Vt[64*132]=8448, addm[128]. Total 21632 floats = 86528 B.
// ---------------------------------------------------------------------------
#define QST 68
#define KST 68
#define PST 132
#define VST 132
#define ATT_SMEM_FLOATS (4352 + 8704 + 8448 + 128)

__global__ __launch_bounds__(128) void attn2_kernel(
    const float* __restrict__ mask, float* __restrict__ out,
    const float* __restrict__ kb, const float* __restrict__ vb)
{
    extern __shared__ float sm[];
    float* Qs   = sm;                  // [64][68]
    float* Ks   = sm + 4352;           // [128][68]
    float* Ps   = Ks;                  // [64][132] aliases Ks
    float* Vt   = sm + 4352 + 8704;    // [64][132] (V transposed: [d][k])
    float* addm = Vt + 8448;           // [128]

    const int tid = threadIdx.x;
    const int ty = tid >> 4, tx = tid & 15;  // ty 0..7, tx 0..15
    const int qi = (gridDim.x - 1) - blockIdx.x;  // long blocks first
    const int h = blockIdx.y, b = blockIdx.z;
    const int q0 = qi * 64;
    const size_t head_off = (((size_t)b * NH + h) * NS) * DH;
    const float* Qg = g_qbuf + head_off;
    const float* Kg = kb + head_off;
    const float* Vg = vb + head_off;

    // Q tile 64x64
#pragma unroll
    for (int p = 0; p < 8; p++) {
        int f = tid + p * 128;
        int r = f >> 4, c4 = (f & 15) * 4;
        *(float4*)&Qs[r * QST + c4] = *(const float4*)&Qg[(size_t)(q0 + r) * DH + c4];
    }

    float o[8][4], mr[8], lr[8];
#pragma unroll
    for (int i = 0; i < 8; i++) {
        mr[i] = -1e30f; lr[i] = 0.0f;
#pragma unroll
        for (int j = 0; j < 4; j++) o[i][j] = 0.0f;
    }
    const float scale = 0.125f;
    const int ntiles = (q0 + 191) >> 7;

    for (int kt = 0; kt < ntiles; kt++) {
        const int k0 = kt * 128;
        __syncthreads();  // previous PV reads of Ps/Vt done; Q visible (iter 0)
        // K tile 128x64 + V transposed 64x128
#pragma unroll
        for (int p = 0; p < 16; p++) {
            int f = tid + p * 128;
            int r = f >> 4, c4 = (f & 15) * 4;
            *(float4*)&Ks[r * KST + c4] = *(const float4*)&Kg[(size_t)(k0 + r) * DH + c4];
            float4 v = *(const float4*)&Vg[(size_t)(k0 + r) * DH + c4];
            Vt[(c4 + 0) * VST + r] = v.x;
            Vt[(c4 + 1) * VST + r] = v.y;
            Vt[(c4 + 2) * VST + r] = v.z;
            Vt[(c4 + 3) * VST + r] = v.w;
        }
        addm[tid] = (1.0f - mask[(size_t)b * NS + k0 + tid]) * (-10000.0f);
        __syncthreads();

        // S = Q @ K^T : s2[i][j], rows q0+ty*8+i, cols k0+tx+16j
        unsigned long long s2[8][8];
#pragma unroll
        for (int i = 0; i < 8; i++)
#pragma unroll
            for (int j = 0; j < 8; j++) s2[i][j] = 0ULL;
#pragma unroll
        for (int d0 = 0; d0 < 64; d0 += 4) {
            unsigned long long a2[8][2], k2[8][2];
#pragma unroll
            for (int i = 0; i < 8; i++) {
                ulonglong2 t = *(const ulonglong2*)&Qs[(ty * 8 + i) * QST + d0];
                a2[i][0] = t.x; a2[i][1] = t.y;
            }
#pragma unroll
            for (int j = 0; j < 8; j++) {
                ulonglong2 t = *(const ulonglong2*)&Ks[(tx + 16 * j) * KST + d0];
                k2[j][0] = t.x; k2[j][1] = t.y;
            }
#pragma unroll
            for (int i = 0; i < 8; i++)
#pragma unroll
                for (int j = 0; j < 8; j++) {
                    FMA2(s2[i][j], a2[i][0], k2[j][0]);
                    FMA2(s2[i][j], a2[i][1], k2[j][1]);
                }
        }

        float am[8];
#pragma unroll
        for (int j = 0; j < 8; j++) am[j] = addm[tx + 16 * j];
        const bool diag = (k0 + 127 > q0);

        float pr[8][8];
#pragma unroll
        for (int i = 0; i < 8; i++) {
            const int r = q0 + ty * 8 + i;
            float mx = -1e30f;
#pragma unroll
            for (int j = 0; j < 8; j++) {
                float v = fmaf(hadd2(s2[i][j]), scale, am[j]);
                if (diag && (k0 + tx + 16 * j > r)) v = -1e30f;
                pr[i][j] = v;
                mx = fmaxf(mx, v);
            }
#pragma unroll
            for (int off = 8; off > 0; off >>= 1)
                mx = fmaxf(mx, __shfl_xor_sync(0xffffffffu, mx, off));
            const float mn = fmaxf(mr[i], mx);
            const float alpha = __expf(mr[i] - mn);
            mr[i] = mn;
            float ps = 0.0f;
#pragma unroll
            for (int j = 0; j < 8; j++) {
                float p = __expf(pr[i][j] - mn);
                pr[i][j] = p;
                ps += p;
            }
#pragma unroll
            for (int off = 8; off > 0; off >>= 1)
                ps += __shfl_xor_sync(0xffffffffu, ps, off);
            lr[i] = lr[i] * alpha + ps;
#pragma unroll
            for (int j = 0; j < 4; j++) o[i][j] *= alpha;
        }

        __syncthreads();  // all Ks reads done -> safe to overwrite with Ps
#pragma unroll
        for (int i = 0; i < 8; i++)
#pragma unroll
            for (int j = 0; j < 8; j++)
                Ps[(ty * 8 + i) * PST + tx + 16 * j] = pr[i][j];
        __syncthreads();

        // O += P @ V : packed over k, V transposed. cols d = tx + 16*jj
        unsigned long long a2v[8][4];
#pragma unroll
        for (int i = 0; i < 8; i++)
#pragma unroll
            for (int j = 0; j < 4; j++) a2v[i][j] = 0ULL;
#pragma unroll
        for (int c0 = 0; c0 < 128; c0 += 4) {
            unsigned long long p2[8][2], v2[4][2];
#pragma unroll
            for (int i = 0; i < 8; i++) {
                ulonglong2 t = *(const ulonglong2*)&Ps[(ty * 8 + i) * PST + c0];
                p2[i][0] = t.x; p2[i][1] = t.y;
            }
#pragma unroll
            for (int j = 0; j < 4; j++) {
                ulonglong2 t = *(const ulonglong2*)&Vt[(tx + 16 * j) * VST + c0];
                v2[j][0] = t.x; v2[j][1] = t.y;
            }
#pragma unroll
            for (int i = 0; i < 8; i++)
#pragma unroll
                for (int j = 0; j < 4; j++) {
                    FMA2(a2v[i][j], p2[i][0], v2[j][0]);
                    FMA2(a2v[i][j], p2[i][1], v2[j][1]);
                }
        }
#pragma unroll
        for (int i = 0; i < 8; i++)
#pragma unroll
            for (int j = 0; j < 4; j++) o[i][j] += hadd2(a2v[i][j]);
    }

    // normalize + merge heads
#pragma unroll
    for (int i = 0; i < 8; i++) {
        const float inv = 1.0f / lr[i];
        const int r = q0 + ty * 8 + i;
        float* orow = out + ((size_t)b * NS + r) * ND + h * DH;
#pragma unroll
        for (int j = 0; j < 4; j++)
            orow[tx + 16 * j] = o[i][j] * inv;
    }
}

extern "C" void kernel_launch(void* const* d_in, const int* in_sizes, int n_in,
                              void* d_out, int out_size) {
    const float* hs   = (const float*)d_in[0];  // [B,S,D]
    const float* mask = (const float*)d_in[1];  // [B,S]
    const float* w    = (const float*)d_in[2];  // [D,3D]
    const float* bias = (const float*)d_in[3];  // [3D]

    float* out = (float*)d_out;
    float* kout = out + (size_t)NB * NS * ND;        // present[0] = K
    float* vout = kout + (size_t)NB * NH * NS * DH;  // present[1] = V

    cudaFuncSetAttribute(attn2_kernel,
                         cudaFuncAttributeMaxDynamicSharedMemorySize,
                         (int)(ATT_SMEM_FLOATS * sizeof(float)));

    // 1) W^T
    wt_kernel<<<dim3(N3 / 32, ND / 32), dim3(32, 8)>>>(w);
    // 2) QKV GEMM (f32x2) + fused bias/scatter
    qkv_gemm2<<<dim3(N3 / 128, MROWS / 128), 256>>>(hs, bias, kout, vout);
    // 3) attention (f32x2)
    attn2_kernel<<<dim3(NS / 64, NH, NB), 128,
                   ATT_SMEM_FLOATS * sizeof(float)>>>(mask, out, kout, vout);
}

// round 4
// speedup vs baseline: 1.7042x; 1.4863x over previous
#include <cuda_runtime.h>
#include <cuda_bf16.h>
#include <cstdint>

#define NB 4
#define NS 2048
#define ND 1024
#define NH 16
#define DH 64
#define N3 3072
#define MROWS (NB * NS)  // 8192

// Device scratch (allocation-free)
__device__ float g_qbuf[(size_t)NB * NH * NS * DH];        // Q [B,H,S,Dh]
__device__ float g_vt[(size_t)NB * NH * DH * NS];          // V^T [B,H,Dh,S]
__device__ __nv_bfloat16 g_ahi[(size_t)MROWS * ND];
__device__ __nv_bfloat16 g_alo[(size_t)MROWS * ND];
__device__ __nv_bfloat16 g_wthi[(size_t)N3 * ND];          // W^T hi [3072,1024]
__device__ __nv_bfloat16 g_wtlo[(size_t)N3 * ND];

// ---------------------------------------------------------------------------
// helpers
// ---------------------------------------------------------------------------
__device__ __forceinline__ uint32_t smem_u32(const void* p) {
    uint32_t a;
    asm("{ .reg .u64 t; cvta.to.shared.u64 t, %1; cvt.u32.u64 %0, t; }"
        : "=r"(a) : "l"(p));
    return a;
}
#define FMA2(c, a, b) \
    asm("fma.rn.f32x2 %0, %1, %2, %0;" : "+l"(c) : "l"(a), "l"(b))
__device__ __forceinline__ float hadd2(unsigned long long v) {
    float lo, hi;
    asm("mov.b64 {%0, %1}, %2;" : "=f"(lo), "=f"(hi) : "l"(v));
    return lo + hi;
}
#define CP_ASYNC16(dst, src) \
    asm volatile("cp.async.cg.shared.global [%0], [%1], 16;" :: "r"(dst), "l"(src))
#define CP_COMMIT() asm volatile("cp.async.commit_group;" ::: "memory")
#define CP_WAIT(n)  asm volatile("cp.async.wait_group %0;" :: "n"(n) : "memory")
#define LDSM4(r, addr) asm volatile( \
    "ldmatrix.sync.aligned.m8n8.x4.shared.b16 {%0,%1,%2,%3}, [%4];" \
    : "=r"((r)[0]), "=r"((r)[1]), "=r"((r)[2]), "=r"((r)[3]) : "r"(addr))
#define MMA_BF16(c, a, b0, b1) asm volatile( \
    "mma.sync.aligned.m16n8k16.row.col.f32.bf16.bf16.f32 " \
    "{%0,%1,%2,%3}, {%4,%5,%6,%7}, {%8,%9}, {%0,%1,%2,%3};" \
    : "+f"((c)[0]), "+f"((c)[1]), "+f"((c)[2]), "+f"((c)[3]) \
    : "r"((a)[0]), "r"((a)[1]), "r"((a)[2]), "r"((a)[3]), "r"(b0), "r"(b1))

// ---------------------------------------------------------------------------
// Prekernel: split A (fp32 -> bf16 hi + lo)
// ---------------------------------------------------------------------------
__global__ __launch_bounds__(256) void split_a_kernel(const float* __restrict__ A) {
    size_t i = ((size_t)blockIdx.x * 256 + threadIdx.x) * 4;
    float4 v = *(const float4*)(A + i);
    __nv_bfloat162 h01 = __floats2bfloat162_rn(v.x, v.y);
    __nv_bfloat162 h23 = __floats2bfloat162_rn(v.z, v.w);
    __nv_bfloat162 l01 = __floats2bfloat162_rn(v.x - __bfloat162float(h01.x),
                                               v.y - __bfloat162float(h01.y));
    __nv_bfloat162 l23 = __floats2bfloat162_rn(v.z - __bfloat162float(h23.x),
                                               v.w - __bfloat162float(h23.y));
    *(__nv_bfloat162*)(g_ahi + i)     = h01;
    *(__nv_bfloat162*)(g_ahi + i + 2) = h23;
    *(__nv_bfloat162*)(g_alo + i)     = l01;
    *(__nv_bfloat162*)(g_alo + i + 2) = l23;
}

// ---------------------------------------------------------------------------
// Prekernel: split + transpose W [1024,3072] -> Wt hi/lo [3072,1024]
// ---------------------------------------------------------------------------
__global__ __launch_bounds__(256) void split_wt_kernel(const float* __restrict__ W) {
    __shared__ float t[32][33];
    const int n0 = blockIdx.x * 32, k0 = blockIdx.y * 32;
    const int tx = threadIdx.x, ty = threadIdx.y;  // 32 x 8
#pragma unroll
    for (int j = 0; j < 4; j++)
        t[ty + j * 8][tx] = W[(size_t)(k0 + ty + j * 8) * N3 + n0 + tx];
    __syncthreads();
#pragma unroll
    for (int j = 0; j < 4; j++) {
        int n = n0 + ty + j * 8, k = k0 + tx;
        float v = t[tx][ty + j * 8];
        __nv_bfloat16 h = __float2bfloat16_rn(v);
        g_wthi[(size_t)n * ND + k] = h;
        g_wtlo[(size_t)n * ND + k] = __float2bfloat16_rn(v - __bfloat162float(h));
    }
}

// ---------------------------------------------------------------------------
// QKV GEMM on HMMA (mma.sync m16n8k16 bf16, 3-term split).
// CTA 128x128, 8 warps (4m x 2n), KC=32 double-buffered cp.async.
// Epilogue: bias + scatter Q->g_qbuf, K->present, V->present AND g_vt (transposed).
// ---------------------------------------------------------------------------
#define GST 40                      // bf16 stride (padded)
#define ARR_B (128 * GST * 2)       // 10240 bytes per array
#define STAGE_B (4 * ARR_B)         // 40960

__global__ __launch_bounds__(256) void qkv_hmma_kernel(
    const float* __restrict__ bias, float* __restrict__ kout, float* __restrict__ vout)
{
    extern __shared__ char gsm[];
    __shared__ float sbias[128];
    const uint32_t sb0 = smem_u32(gsm);
    const int tid = threadIdx.x;
    const int wid = tid >> 5, lane = tid & 31;
    const int wm = wid >> 1, wn = wid & 1;
    const int m0 = blockIdx.y * 128, n0 = blockIdx.x * 128;

    if (tid < 128) sbias[tid] = bias[n0 + tid];

    const __nv_bfloat16* gAh = g_ahi + (size_t)m0 * ND;
    const __nv_bfloat16* gAl = g_alo + (size_t)m0 * ND;
    const __nv_bfloat16* gBh = g_wthi + (size_t)n0 * ND;
    const __nv_bfloat16* gBl = g_wtlo + (size_t)n0 * ND;

    // per-thread cp.async line coords: 512 lines of 16B per array
    const int l0 = tid, l1 = tid + 256;
    const int r0g = l0 >> 2, c0g = (l0 & 3) * 8;   // row, bf16 col
    const int r1g = l1 >> 2, c1g = (l1 & 3) * 8;

    float acc[2][8][4];
#pragma unroll
    for (int mt = 0; mt < 2; mt++)
#pragma unroll
        for (int nt = 0; nt < 8; nt++)
#pragma unroll
            for (int e = 0; e < 4; e++) acc[mt][nt][e] = 0.0f;

    // ldmatrix per-lane address components
    const int lrA = lane & 15, hkA = (lane >> 4) * 8;
    const int lrB = (lane & 7) + ((lane >> 4) & 1) * 8;
    const int hkB = ((lane >> 3) & 1) * 8;

#define LOAD_STAGE(kc, buf) do { \
    uint32_t d = sb0 + (buf) * STAGE_B; \
    size_t ga0 = (size_t)r0g * ND + (kc) * 32 + c0g; \
    size_t ga1 = (size_t)r1g * ND + (kc) * 32 + c1g; \
    uint32_t s0 = (uint32_t)(r0g * GST + c0g) * 2; \
    uint32_t s1 = (uint32_t)(r1g * GST + c1g) * 2; \
    CP_ASYNC16(d + s0,             gAh + ga0); \
    CP_ASYNC16(d + s1,             gAh + ga1); \
    CP_ASYNC16(d + ARR_B + s0,     gAl + ga0); \
    CP_ASYNC16(d + ARR_B + s1,     gAl + ga1); \
    CP_ASYNC16(d + 2 * ARR_B + s0, gBh + ga0); \
    CP_ASYNC16(d + 2 * ARR_B + s1, gBh + ga1); \
    CP_ASYNC16(d + 3 * ARR_B + s0, gBl + ga0); \
    CP_ASYNC16(d + 3 * ARR_B + s1, gBl + ga1); \
} while (0)

    LOAD_STAGE(0, 0);
    CP_COMMIT();

    for (int kc = 0; kc < ND / 32; kc++) {
        const int buf = kc & 1;
        if (kc + 1 < ND / 32) {
            LOAD_STAGE(kc + 1, buf ^ 1);
            CP_COMMIT();
            CP_WAIT(1);
        } else {
            CP_WAIT(0);
        }
        __syncthreads();

        const uint32_t sbuf = sb0 + buf * STAGE_B;
#pragma unroll
        for (int kk = 0; kk < 2; kk++) {
            uint32_t ah[2][4], al[2][4], bh[16], bl[16];
#pragma unroll
            for (int mt = 0; mt < 2; mt++) {
                uint32_t a = sbuf +
                    (uint32_t)((wm * 32 + mt * 16 + lrA) * GST + kk * 16 + hkA) * 2;
                LDSM4(ah[mt], a);
                LDSM4(al[mt], a + ARR_B);
            }
#pragma unroll
            for (int nt2 = 0; nt2 < 4; nt2++) {
                uint32_t a = sbuf + 2 * ARR_B +
                    (uint32_t)((wn * 64 + nt2 * 16 + lrB) * GST + kk * 16 + hkB) * 2;
                LDSM4(&bh[nt2 * 4], a);
                LDSM4(&bl[nt2 * 4], a + ARR_B);
            }
#pragma unroll
            for (int mt = 0; mt < 2; mt++)
#pragma unroll
                for (int nt = 0; nt < 8; nt++) {
                    MMA_BF16(acc[mt][nt], ah[mt], bh[nt * 2], bh[nt * 2 + 1]);
                    MMA_BF16(acc[mt][nt], ah[mt], bl[nt * 2], bl[nt * 2 + 1]);
                    MMA_BF16(acc[mt][nt], al[mt], bh[nt * 2], bh[nt * 2 + 1]);
                }
        }
        __syncthreads();
    }

    // Epilogue: bias + head-split scatter (+ transposed V copy)
    const int sel = n0 >> 10;
    float* dst = (sel == 0) ? g_qbuf : ((sel == 1) ? kout : vout);
    const int rl = lane >> 2, cpair = (lane & 3) * 2;
#pragma unroll
    for (int mt = 0; mt < 2; mt++) {
#pragma unroll
        for (int half = 0; half < 2; half++) {
            const int m = m0 + wm * 32 + mt * 16 + rl + half * 8;
            const int b = m >> 11, s = m & (NS - 1);
#pragma unroll
            for (int nt = 0; nt < 8; nt++) {
                const int coln = wn * 64 + nt * 8 + cpair;
                const int h = ((n0 & (ND - 1)) >> 6) + (coln >> 6);
                const int d = coln & 63;
                const float v0 = acc[mt][nt][half * 2 + 0] + sbias[coln];
                const float v1 = acc[mt][nt][half * 2 + 1] + sbias[coln + 1];
                float2 o = make_float2(v0, v1);
                *(float2*)&dst[((((size_t)b * NH + h) * NS + s) * DH) + d] = o;
                if (sel == 2) {
                    float* vt = g_vt + (((size_t)b * NH + h) * DH) * NS;
                    vt[(size_t)d * NS + s] = v0;
                    vt[(size_t)(d + 1) * NS + s] = v1;
                }
            }
        }
    }
}

// ---------------------------------------------------------------------------
// Flash attention, FFMA2, 256 threads. Bq=64, Bk=128.
// QK^T: 4x8/thread k-packed. PV: 4x4/thread k-packed, V^T from g_vt.
// P aliases K smem. Online softmax.
// ---------------------------------------------------------------------------
#define QST 68
#define KST 68
#define PST 132
#define VST 132
#define ATT_SMEM_FLOATS (4352 + 8704 + 8448 + 128)

__global__ __launch_bounds__(256) void attn2_kernel(
    const float* __restrict__ mask, float* __restrict__ out,
    const float* __restrict__ kb)
{
    extern __shared__ float sm[];
    float* Qs   = sm;                  // [64][68]
    float* Ks   = sm + 4352;           // [128][68]
    float* Ps   = Ks;                  // [64][132] aliases Ks
    float* Vt   = sm + 4352 + 8704;    // [64][132]  ([d][k])
    float* addm = Vt + 8448;           // [128]

    const int tid = threadIdx.x;
    const int ty = tid >> 4, tx = tid & 15;       // ty 0..15, tx 0..15
    const int qi = (gridDim.x - 1) - blockIdx.x;  // long blocks first
    const int h = blockIdx.y, b = blockIdx.z;
    const int q0 = qi * 64;
    const size_t head_off = (((size_t)b * NH + h) * NS) * DH;
    const float* Qg = g_qbuf + head_off;
    const float* Kg = kb + head_off;
    const float* Vtg = g_vt + (((size_t)b * NH + h) * DH) * NS;

    // Q tile 64x64 (1024 float4 / 256 thr = 4)
#pragma unroll
    for (int p = 0; p < 4; p++) {
        int f = tid + p * 256;
        int r = f >> 4, c4 = (f & 15) * 4;
        *(float4*)&Qs[r * QST + c4] = *(const float4*)&Qg[(size_t)(q0 + r) * DH + c4];
    }

    float o[4][4], mr[4], lr[4];
#pragma unroll
    for (int i = 0; i < 4; i++) {
        mr[i] = -1e30f; lr[i] = 0.0f;
#pragma unroll
        for (int j = 0; j < 4; j++) o[i][j] = 0.0f;
    }
    const float scale = 0.125f;
    const int ntiles = (q0 + 191) >> 7;

    for (int kt = 0; kt < ntiles; kt++) {
        const int k0 = kt * 128;
        __syncthreads();
        // K tile 128x64 (2048 float4 / 256 = 8)
#pragma unroll
        for (int p = 0; p < 8; p++) {
            int f = tid + p * 256;
            int r = f >> 4, c4 = (f & 15) * 4;
            *(float4*)&Ks[r * KST + c4] = *(const float4*)&Kg[(size_t)(k0 + r) * DH + c4];
        }
        // V^T tile 64x128 (2048 float4 / 256 = 8), row-wise from g_vt
#pragma unroll
        for (int p = 0; p < 8; p++) {
            int f = tid + p * 256;
            int r = f >> 5, c4 = (f & 31) * 4;
            *(float4*)&Vt[r * VST + c4] = *(const float4*)&Vtg[(size_t)r * NS + k0 + c4];
        }
        if (tid < 128)
            addm[tid] = (1.0f - mask[(size_t)b * NS + k0 + tid]) * (-10000.0f);
        __syncthreads();

        // S = Q @ K^T : rows q0+ty*4+i, cols k0+tx+16j
        unsigned long long s2[4][8];
#pragma unroll
        for (int i = 0; i < 4; i++)
#pragma unroll
            for (int j = 0; j < 8; j++) s2[i][j] = 0ULL;
#pragma unroll
        for (int d0 = 0; d0 < 64; d0 += 4) {
            unsigned long long a2[4][2], k2[8][2];
#pragma unroll
            for (int i = 0; i < 4; i++) {
                ulonglong2 t = *(const ulonglong2*)&Qs[(ty * 4 + i) * QST + d0];
                a2[i][0] = t.x; a2[i][1] = t.y;
            }
#pragma unroll
            for (int j = 0; j < 8; j++) {
                ulonglong2 t = *(const ulonglong2*)&Ks[(tx + 16 * j) * KST + d0];
                k2[j][0] = t.x; k2[j][1] = t.y;
            }
#pragma unroll
            for (int i = 0; i < 4; i++)
#pragma unroll
                for (int j = 0; j < 8; j++) {
                    FMA2(s2[i][j], a2[i][0], k2[j][0]);
                    FMA2(s2[i][j], a2[i][1], k2[j][1]);
                }
        }

        float am[8];
#pragma unroll
        for (int j = 0; j < 8; j++) am[j] = addm[tx + 16 * j];
        const bool diag = (k0 + 127 > q0);

        float pr[4][8];
#pragma unroll
        for (int i = 0; i < 4; i++) {
            const int r = q0 + ty * 4 + i;
            float mx = -1e30f;
#pragma unroll
            for (int j = 0; j < 8; j++) {
                float v = fmaf(hadd2(s2[i][j]), scale, am[j]);
                if (diag && (k0 + tx + 16 * j > r)) v = -1e30f;
                pr[i][j] = v;
                mx = fmaxf(mx, v);
            }
#pragma unroll
            for (int off = 8; off > 0; off >>= 1)
                mx = fmaxf(mx, __shfl_xor_sync(0xffffffffu, mx, off));
            const float mn = fmaxf(mr[i], mx);
            const float alpha = __expf(mr[i] - mn);
            mr[i] = mn;
            float ps = 0.0f;
#pragma unroll
            for (int j = 0; j < 8; j++) {
                float p = __expf(pr[i][j] - mn);
                pr[i][j] = p;
                ps += p;
            }
#pragma unroll
            for (int off = 8; off > 0; off >>= 1)
                ps += __shfl_xor_sync(0xffffffffu, ps, off);
            lr[i] = lr[i] * alpha + ps;
#pragma unroll
            for (int j = 0; j < 4; j++) o[i][j] *= alpha;
        }

        __syncthreads();  // Ks reads done -> overwrite with Ps
#pragma unroll
        for (int i = 0; i < 4; i++)
#pragma unroll
            for (int j = 0; j < 8; j++)
                Ps[(ty * 4 + i) * PST + tx + 16 * j] = pr[i][j];
        __syncthreads();

        // O += P @ V : cols d = tx + 16*j (j<4), k-packed
        unsigned long long a2v[4][4];
#pragma unroll
        for (int i = 0; i < 4; i++)
#pragma unroll
            for (int j = 0; j < 4; j++) a2v[i][j] = 0ULL;
#pragma unroll
        for (int c0 = 0; c0 < 128; c0 += 4) {
            unsigned long long p2[4][2], v2[4][2];
#pragma unroll
            for (int i = 0; i < 4; i++) {
                ulonglong2 t = *(const ulonglong2*)&Ps[(ty * 4 + i) * PST + c0];
                p2[i][0] = t.x; p2[i][1] = t.y;
            }
#pragma unroll
            for (int j = 0; j < 4; j++) {
                ulonglong2 t = *(const ulonglong2*)&Vt[(tx + 16 * j) * VST + c0];
                v2[j][0] = t.x; v2[j][1] = t.y;
            }
#pragma unroll
            for (int i = 0; i < 4; i++)
#pragma unroll
                for (int j = 0; j < 4; j++) {
                    FMA2(a2v[i][j], p2[i][0], v2[j][0]);
                    FMA2(a2v[i][j], p2[i][1], v2[j][1]);
                }
        }
#pragma unroll
        for (int i = 0; i < 4; i++)
#pragma unroll
            for (int j = 0; j < 4; j++) o[i][j] += hadd2(a2v[i][j]);
    }

    // normalize + merge heads
#pragma unroll
    for (int i = 0; i < 4; i++) {
        const float inv = 1.0f / lr[i];
        const int r = q0 + ty * 4 + i;
        float* orow = out + ((size_t)b * NS + r) * ND + h * DH;
#pragma unroll
        for (int j = 0; j < 4; j++)
            orow[tx + 16 * j] = o[i][j] * inv;
    }
}

extern "C" void kernel_launch(void* const* d_in, const int* in_sizes, int n_in,
                              void* d_out, int out_size) {
    const float* hs   = (const float*)d_in[0];  // [B,S,D]
    const float* mask = (const float*)d_in[1];  // [B,S]
    const float* w    = (const float*)d_in[2];  // [D,3D]
    const float* bias = (const float*)d_in[3];  // [3D]

    float* out = (float*)d_out;
    float* kout = out + (size_t)NB * NS * ND;        // present[0] = K
    float* vout = kout + (size_t)NB * NH * NS * DH;  // present[1] = V

    cudaFuncSetAttribute(qkv_hmma_kernel,
                         cudaFuncAttributeMaxDynamicSharedMemorySize, 2 * STAGE_B);
    cudaFuncSetAttribute(attn2_kernel,
                         cudaFuncAttributeMaxDynamicSharedMemorySize,
                         (int)(ATT_SMEM_FLOATS * sizeof(float)));

    // 1) bf16 hi/lo split of A and W^T
    split_a_kernel<<<(MROWS * ND) / (256 * 4), 256>>>(hs);
    split_wt_kernel<<<dim3(N3 / 32, ND / 32), dim3(32, 8)>>>(w);
    // 2) HMMA QKV GEMM (+ bias, head-split scatter, transposed V)
    qkv_hmma_kernel<<<dim3(N3 / 128, MROWS / 128), 256, 2 * STAGE_B>>>(
        bias, kout, vout);
    // 3) attention (FFMA2)
    attn2_kernel<<<dim3(NS / 64, NH, NB), 256,
                   ATT_SMEM_FLOATS * sizeof(float)>>>(mask, out, kout);
}

// round 5
// speedup vs baseline: 3.0499x; 1.7896x over previous
#include <cuda_runtime.h>
#include <cuda_bf16.h>
#include <cstdint>

#define NB 4
#define NS 2048
#define ND 1024
#define NH 16
#define DH 64
#define N3 3072
#define MROWS (NB * NS)  // 8192

// Device scratch (allocation-free)
__device__ __nv_bfloat16 g_ahi[(size_t)MROWS * ND];
__device__ __nv_bfloat16 g_alo[(size_t)MROWS * ND];
__device__ __nv_bfloat16 g_wthi[(size_t)N3 * ND];   // W^T hi [3072,1024]
__device__ __nv_bfloat16 g_wtlo[(size_t)N3 * ND];
__device__ __nv_bfloat16 g_qh[(size_t)NB * NH * NS * DH];   // Q hi [B,H,S,Dh]
__device__ __nv_bfloat16 g_ql[(size_t)NB * NH * NS * DH];
__device__ __nv_bfloat16 g_kh[(size_t)NB * NH * NS * DH];   // K hi [B,H,S,Dh]
__device__ __nv_bfloat16 g_kl[(size_t)NB * NH * NS * DH];
__device__ __nv_bfloat16 g_vth[(size_t)NB * NH * DH * NS];  // V^T hi [B,H,Dh,S]
__device__ __nv_bfloat16 g_vtl[(size_t)NB * NH * DH * NS];

// ---------------------------------------------------------------------------
// helpers
// ---------------------------------------------------------------------------
__device__ __forceinline__ uint32_t smem_u32(const void* p) {
    uint32_t a;
    asm("{ .reg .u64 t; cvta.to.shared.u64 t, %1; cvt.u32.u64 %0, t; }"
        : "=r"(a) : "l"(p));
    return a;
}
#define CP_ASYNC16(dst, src) \
    asm volatile("cp.async.cg.shared.global [%0], [%1], 16;" :: "r"(dst), "l"(src))
#define CP_COMMIT() asm volatile("cp.async.commit_group;" ::: "memory")
#define CP_WAIT(n)  asm volatile("cp.async.wait_group %0;" :: "n"(n) : "memory")
#define LDSM4(r, addr) asm volatile( \
    "ldmatrix.sync.aligned.m8n8.x4.shared.b16 {%0,%1,%2,%3}, [%4];" \
    : "=r"((r)[0]), "=r"((r)[1]), "=r"((r)[2]), "=r"((r)[3]) : "r"(addr))
#define MMA_BF16(c, a, b0, b1) asm volatile( \
    "mma.sync.aligned.m16n8k16.row.col.f32.bf16.bf16.f32 " \
    "{%0,%1,%2,%3}, {%4,%5,%6,%7}, {%8,%9}, {%0,%1,%2,%3};" \
    : "+f"((c)[0]), "+f"((c)[1]), "+f"((c)[2]), "+f"((c)[3]) \
    : "r"((a)[0]), "r"((a)[1]), "r"((a)[2]), "r"((a)[3]), "r"(b0), "r"(b1))

// ---------------------------------------------------------------------------
// Prekernel: split A (fp32 -> bf16 hi + lo)
// ---------------------------------------------------------------------------
__global__ __launch_bounds__(256) void split_a_kernel(const float* __restrict__ A) {
    size_t i = ((size_t)blockIdx.x * 256 + threadIdx.x) * 4;
    float4 v = *(const float4*)(A + i);
    __nv_bfloat162 h01 = __floats2bfloat162_rn(v.x, v.y);
    __nv_bfloat162 h23 = __floats2bfloat162_rn(v.z, v.w);
    __nv_bfloat162 l01 = __floats2bfloat162_rn(v.x - __bfloat162float(h01.x),
                                               v.y - __bfloat162float(h01.y));
    __nv_bfloat162 l23 = __floats2bfloat162_rn(v.z - __bfloat162float(h23.x),
                                               v.w - __bfloat162float(h23.y));
    *(__nv_bfloat162*)(g_ahi + i)     = h01;
    *(__nv_bfloat162*)(g_ahi + i + 2) = h23;
    *(__nv_bfloat162*)(g_alo + i)     = l01;
    *(__nv_bfloat162*)(g_alo + i + 2) = l23;
}

// ---------------------------------------------------------------------------
// Prekernel: split + transpose W [1024,3072] -> Wt hi/lo [3072,1024]
// ---------------------------------------------------------------------------
__global__ __launch_bounds__(256) void split_wt_kernel(const float* __restrict__ W) {
    __shared__ float t[32][33];
    const int n0 = blockIdx.x * 32, k0 = blockIdx.y * 32;
    const int tx = threadIdx.x, ty = threadIdx.y;  // 32 x 8
#pragma unroll
    for (int j = 0; j < 4; j++)
        t[ty + j * 8][tx] = W[(size_t)(k0 + ty + j * 8) * N3 + n0 + tx];
    __syncthreads();
#pragma unroll
    for (int j = 0; j < 4; j++) {
        int n = n0 + ty + j * 8, k = k0 + tx;
        float v = t[tx][ty + j * 8];
        __nv_bfloat16 h = __float2bfloat16_rn(v);
        g_wthi[(size_t)n * ND + k] = h;
        g_wtlo[(size_t)n * ND + k] = __float2bfloat16_rn(v - __bfloat162float(h));
    }
}

// ---------------------------------------------------------------------------
// QKV GEMM on HMMA (3-term bf16 split). CTA 128x128, 8 warps, KC=32 cp.async.
// Epilogue: bias; Q -> bf16 hi/lo; K -> fp32 present + bf16 hi/lo;
//           V -> fp32 present + transposed bf16 hi/lo.
// ---------------------------------------------------------------------------
#define GST 40                      // bf16 smem stride
#define ARR_B (128 * GST * 2)       // 10240 B per array
#define STAGE_B (4 * ARR_B)         // 40960

__global__ __launch_bounds__(256) void qkv_hmma_kernel(
    const float* __restrict__ bias, float* __restrict__ kout, float* __restrict__ vout)
{
    extern __shared__ char gsm[];
    __shared__ float sbias[128];
    const uint32_t sb0 = smem_u32(gsm);
    const int tid = threadIdx.x;
    const int wid = tid >> 5, lane = tid & 31;
    const int wm = wid >> 1, wn = wid & 1;
    const int m0 = blockIdx.y * 128, n0 = blockIdx.x * 128;

    if (tid < 128) sbias[tid] = bias[n0 + tid];

    const __nv_bfloat16* gAh = g_ahi + (size_t)m0 * ND;
    const __nv_bfloat16* gAl = g_alo + (size_t)m0 * ND;
    const __nv_bfloat16* gBh = g_wthi + (size_t)n0 * ND;
    const __nv_bfloat16* gBl = g_wtlo + (size_t)n0 * ND;

    const int l0 = tid, l1 = tid + 256;
    const int r0g = l0 >> 2, c0g = (l0 & 3) * 8;
    const int r1g = l1 >> 2, c1g = (l1 & 3) * 8;

    float acc[2][8][4];
#pragma unroll
    for (int mt = 0; mt < 2; mt++)
#pragma unroll
        for (int nt = 0; nt < 8; nt++)
#pragma unroll
            for (int e = 0; e < 4; e++) acc[mt][nt][e] = 0.0f;

    const int lrA = lane & 15, hkA = (lane >> 4) * 8;
    const int lrB = (lane & 7) + ((lane >> 4) & 1) * 8;
    const int hkB = ((lane >> 3) & 1) * 8;

#define LOAD_STAGE(kc, buf) do { \
    uint32_t d = sb0 + (buf) * STAGE_B; \
    size_t ga0 = (size_t)r0g * ND + (kc) * 32 + c0g; \
    size_t ga1 = (size_t)r1g * ND + (kc) * 32 + c1g; \
    uint32_t s0 = (uint32_t)(r0g * GST + c0g) * 2; \
    uint32_t s1 = (uint32_t)(r1g * GST + c1g) * 2; \
    CP_ASYNC16(d + s0,             gAh + ga0); \
    CP_ASYNC16(d + s1,             gAh + ga1); \
    CP_ASYNC16(d + ARR_B + s0,     gAl + ga0); \
    CP_ASYNC16(d + ARR_B + s1,     gAl + ga1); \
    CP_ASYNC16(d + 2 * ARR_B + s0, gBh + ga0); \
    CP_ASYNC16(d + 2 * ARR_B + s1, gBh + ga1); \
    CP_ASYNC16(d + 3 * ARR_B + s0, gBl + ga0); \
    CP_ASYNC16(d + 3 * ARR_B + s1, gBl + ga1); \
} while (0)

    LOAD_STAGE(0, 0);
    CP_COMMIT();

    for (int kc = 0; kc < ND / 32; kc++) {
        const int buf = kc & 1;
        if (kc + 1 < ND / 32) {
            LOAD_STAGE(kc + 1, buf ^ 1);
            CP_COMMIT();
            CP_WAIT(1);
        } else {
            CP_WAIT(0);
        }
        __syncthreads();

        const uint32_t sbuf = sb0 + buf * STAGE_B;
#pragma unroll
        for (int kk = 0; kk < 2; kk++) {
            uint32_t ah[2][4], al[2][4], bh[16], bl[16];
#pragma unroll
            for (int mt = 0; mt < 2; mt++) {
                uint32_t a = sbuf +
                    (uint32_t)((wm * 32 + mt * 16 + lrA) * GST + kk * 16 + hkA) * 2;
                LDSM4(ah[mt], a);
                LDSM4(al[mt], a + ARR_B);
            }
#pragma unroll
            for (int nt2 = 0; nt2 < 4; nt2++) {
                uint32_t a = sbuf + 2 * ARR_B +
                    (uint32_t)((wn * 64 + nt2 * 16 + lrB) * GST + kk * 16 + hkB) * 2;
                LDSM4(&bh[nt2 * 4], a);
                LDSM4(&bl[nt2 * 4], a + ARR_B);
            }
#pragma unroll
            for (int mt = 0; mt < 2; mt++)
#pragma unroll
                for (int nt = 0; nt < 8; nt++) {
                    MMA_BF16(acc[mt][nt], ah[mt], bh[nt * 2], bh[nt * 2 + 1]);
                    MMA_BF16(acc[mt][nt], ah[mt], bl[nt * 2], bl[nt * 2 + 1]);
                    MMA_BF16(acc[mt][nt], al[mt], bh[nt * 2], bh[nt * 2 + 1]);
                }
        }
        __syncthreads();
    }

    // Epilogue
    const int sel = n0 >> 10;
    const int rl = lane >> 2, cpair = (lane & 3) * 2;
#pragma unroll
    for (int mt = 0; mt < 2; mt++) {
#pragma unroll
        for (int half = 0; half < 2; half++) {
            const int m = m0 + wm * 32 + mt * 16 + rl + half * 8;
            const int b = m >> 11, s = m & (NS - 1);
#pragma unroll
            for (int nt = 0; nt < 8; nt++) {
                const int coln = wn * 64 + nt * 8 + cpair;
                const int h = ((n0 & (ND - 1)) >> 6) + (coln >> 6);
                const int d = coln & 63;
                const float v0 = acc[mt][nt][half * 2 + 0] + sbias[coln];
                const float v1 = acc[mt][nt][half * 2 + 1] + sbias[coln + 1];
                const size_t idx = (((size_t)b * NH + h) * NS + s) * DH + d;
                __nv_bfloat162 hh = __floats2bfloat162_rn(v0, v1);
                __nv_bfloat162 ll = __floats2bfloat162_rn(
                    v0 - __bfloat162float(hh.x), v1 - __bfloat162float(hh.y));
                if (sel == 0) {
                    *(__nv_bfloat162*)&g_qh[idx] = hh;
                    *(__nv_bfloat162*)&g_ql[idx] = ll;
                } else if (sel == 1) {
                    *(float2*)&kout[idx] = make_float2(v0, v1);
                    *(__nv_bfloat162*)&g_kh[idx] = hh;
                    *(__nv_bfloat162*)&g_kl[idx] = ll;
                } else {
                    *(float2*)&vout[idx] = make_float2(v0, v1);
                    const size_t ti = (((size_t)b * NH + h) * DH + d) * NS + s;
                    g_vth[ti] = hh.x; g_vth[ti + NS] = hh.y;
                    g_vtl[ti] = ll.x; g_vtl[ti + NS] = ll.y;
                }
            }
        }
    }
}

// ---------------------------------------------------------------------------
// Flash attention on HMMA. Bq=Bk=64, 4 warps (16 q-rows each), 3-term bf16
// split for QK^T and PV, softmax on MMA fragments, per-warp P staging.
// ---------------------------------------------------------------------------
#define AS 72  // bf16 smem stride
#define ATT_SMEM_B (8 * 64 * AS * 2 + 256)

__global__ __launch_bounds__(128) void attn_hmma_kernel(
    const float* __restrict__ mask, float* __restrict__ out)
{
    extern __shared__ __nv_bfloat16 sb[];
    __nv_bfloat16* Qh = sb;
    __nv_bfloat16* Ql = sb + 1 * 64 * AS;
    __nv_bfloat16* Kh = sb + 2 * 64 * AS;
    __nv_bfloat16* Kl = sb + 3 * 64 * AS;
    __nv_bfloat16* Vh = sb + 4 * 64 * AS;
    __nv_bfloat16* Vl = sb + 5 * 64 * AS;
    __nv_bfloat16* Ph = sb + 6 * 64 * AS;
    __nv_bfloat16* Pl = sb + 7 * 64 * AS;
    float* addm = (float*)(sb + 8 * 64 * AS);

    const int tid = threadIdx.x;
    const int w = tid >> 5, lane = tid & 31;
    const int qi = (gridDim.x - 1) - blockIdx.x;  // long blocks first
    const int h = blockIdx.y, b = blockIdx.z;
    const int q0 = qi * 64;
    const size_t hoff = (((size_t)b * NH + h) * NS) * DH;
    const __nv_bfloat16* gQh = g_qh + hoff + (size_t)q0 * DH;
    const __nv_bfloat16* gQl = g_ql + hoff + (size_t)q0 * DH;
    const __nv_bfloat16* gKh = g_kh + hoff;
    const __nv_bfloat16* gKl = g_kl + hoff;
    const size_t voff = (((size_t)b * NH + h) * DH) * NS;
    const __nv_bfloat16* gVh = g_vth + voff;
    const __nv_bfloat16* gVl = g_vtl + voff;

    // Q tile (once): 64 rows x 8 x 16B lines per matrix
#pragma unroll
    for (int p = 0; p < 4; p++) {
        int f = tid + p * 128;
        int r = f >> 3, ln = (f & 7) * 8;
        *(uint4*)&Qh[r * AS + ln] = *(const uint4*)&gQh[(size_t)r * DH + ln];
        *(uint4*)&Ql[r * AS + ln] = *(const uint4*)&gQl[(size_t)r * DH + ln];
    }

    const int lrA = lane & 15, hkA = (lane >> 4) * 8;
    const int lrB = (lane & 7) + ((lane >> 4) & 1) * 8;
    const int hkB = ((lane >> 3) & 1) * 8;
    const int rq = lane >> 2, cq = (lane & 3) * 2;

    const uint32_t uQh = smem_u32(Qh), uQl = smem_u32(Ql);
    const uint32_t uKh = smem_u32(Kh), uKl = smem_u32(Kl);
    const uint32_t uVh = smem_u32(Vh), uVl = smem_u32(Vl);
    const uint32_t uPh = smem_u32(Ph), uPl = smem_u32(Pl);

    float oacc[8][4];
#pragma unroll
    for (int nt = 0; nt < 8; nt++)
#pragma unroll
        for (int e = 0; e < 4; e++) oacc[nt][e] = 0.0f;
    float m2[2] = {-1e30f, -1e30f}, l2[2] = {0.0f, 0.0f};
    const float scale = 0.125f;

    for (int kt = 0; kt <= qi; kt++) {
        const int k0 = kt * 64;
        __syncthreads();
#pragma unroll
        for (int p = 0; p < 4; p++) {
            int f = tid + p * 128;
            int r = f >> 3, ln = (f & 7) * 8;
            *(uint4*)&Kh[r * AS + ln] = *(const uint4*)&gKh[(size_t)(k0 + r) * DH + ln];
            *(uint4*)&Kl[r * AS + ln] = *(const uint4*)&gKl[(size_t)(k0 + r) * DH + ln];
            *(uint4*)&Vh[r * AS + ln] = *(const uint4*)&gVh[(size_t)r * NS + k0 + ln];
            *(uint4*)&Vl[r * AS + ln] = *(const uint4*)&gVl[(size_t)r * NS + k0 + ln];
        }
        if (tid < 64)
            addm[tid] = (1.0f - mask[(size_t)b * NS + k0 + tid]) * (-10000.0f);
        __syncthreads();

        // S = Q @ K^T (3-term split)
        float sacc[8][4];
#pragma unroll
        for (int nt = 0; nt < 8; nt++)
#pragma unroll
            for (int e = 0; e < 4; e++) sacc[nt][e] = 0.0f;
#pragma unroll
        for (int kk = 0; kk < 4; kk++) {
            uint32_t ah[4], al[4], bh[16], bl[16];
            const uint32_t aoff = (uint32_t)((w * 16 + lrA) * AS + kk * 16 + hkA) * 2;
            LDSM4(ah, uQh + aoff);
            LDSM4(al, uQl + aoff);
#pragma unroll
            for (int t2 = 0; t2 < 4; t2++) {
                const uint32_t boff =
                    (uint32_t)((t2 * 16 + lrB) * AS + kk * 16 + hkB) * 2;
                LDSM4(&bh[t2 * 4], uKh + boff);
                LDSM4(&bl[t2 * 4], uKl + boff);
            }
#pragma unroll
            for (int nt = 0; nt < 8; nt++) {
                MMA_BF16(sacc[nt], ah, bh[nt * 2], bh[nt * 2 + 1]);
                MMA_BF16(sacc[nt], ah, bl[nt * 2], bl[nt * 2 + 1]);
                MMA_BF16(sacc[nt], al, bh[nt * 2], bh[nt * 2 + 1]);
            }
        }

        const bool diag = (kt == qi);
        float am0[8], am1[8];
#pragma unroll
        for (int nt = 0; nt < 8; nt++) {
            am0[nt] = addm[nt * 8 + cq];
            am1[nt] = addm[nt * 8 + cq + 1];
        }

#pragma unroll
        for (int hi = 0; hi < 2; hi++) {
            const int row = q0 + w * 16 + rq + hi * 8;
            float pv[8][2];
            float mx = -1e30f;
#pragma unroll
            for (int nt = 0; nt < 8; nt++) {
                float v0 = fmaf(sacc[nt][hi * 2 + 0], scale, am0[nt]);
                float v1 = fmaf(sacc[nt][hi * 2 + 1], scale, am1[nt]);
                if (diag && (k0 + nt * 8 + cq + 0 > row)) v0 = -1e30f;
                if (diag && (k0 + nt * 8 + cq + 1 > row)) v1 = -1e30f;
                pv[nt][0] = v0; pv[nt][1] = v1;
                mx = fmaxf(mx, fmaxf(v0, v1));
            }
            mx = fmaxf(mx, __shfl_xor_sync(0xffffffffu, mx, 1));
            mx = fmaxf(mx, __shfl_xor_sync(0xffffffffu, mx, 2));
            const float mn = fmaxf(m2[hi], mx);
            const float alpha = __expf(m2[hi] - mn);
            m2[hi] = mn;
            float ps = 0.0f;
            const int rl = w * 16 + rq + hi * 8;
#pragma unroll
            for (int nt = 0; nt < 8; nt++) {
                float p0 = __expf(pv[nt][0] - mn);
                float p1 = __expf(pv[nt][1] - mn);
                ps += p0 + p1;
                __nv_bfloat162 hh = __floats2bfloat162_rn(p0, p1);
                __nv_bfloat162 ll = __floats2bfloat162_rn(
                    p0 - __bfloat162float(hh.x), p1 - __bfloat162float(hh.y));
                *(__nv_bfloat162*)&Ph[rl * AS + nt * 8 + cq] = hh;
                *(__nv_bfloat162*)&Pl[rl * AS + nt * 8 + cq] = ll;
            }
            ps += __shfl_xor_sync(0xffffffffu, ps, 1);
            ps += __shfl_xor_sync(0xffffffffu, ps, 2);
            l2[hi] = l2[hi] * alpha + ps;
#pragma unroll
            for (int nt = 0; nt < 8; nt++) {
                oacc[nt][hi * 2 + 0] *= alpha;
                oacc[nt][hi * 2 + 1] *= alpha;
            }
        }
        __syncwarp();  // P rows are per-warp; make them visible to ldmatrix

        // O += P @ V (3-term split)
#pragma unroll
        for (int kk = 0; kk < 4; kk++) {
            uint32_t ah[4], al[4], bh[16], bl[16];
            const uint32_t aoff = (uint32_t)((w * 16 + lrA) * AS + kk * 16 + hkA) * 2;
            LDSM4(ah, uPh + aoff);
            LDSM4(al, uPl + aoff);
#pragma unroll
            for (int t2 = 0; t2 < 4; t2++) {
                const uint32_t boff =
                    (uint32_t)((t2 * 16 + lrB) * AS + kk * 16 + hkB) * 2;
                LDSM4(&bh[t2 * 4], uVh + boff);
                LDSM4(&bl[t2 * 4], uVl + boff);
            }
#pragma unroll
            for (int nt = 0; nt < 8; nt++) {
                MMA_BF16(oacc[nt], ah, bh[nt * 2], bh[nt * 2 + 1]);
                MMA_BF16(oacc[nt], ah, bl[nt * 2], bl[nt * 2 + 1]);
                MMA_BF16(oacc[nt], al, bh[nt * 2], bh[nt * 2 + 1]);
            }
        }
    }

    // normalize + merge heads
#pragma unroll
    for (int hi = 0; hi < 2; hi++) {
        const int row = q0 + w * 16 + rq + hi * 8;
        const float inv = 1.0f / l2[hi];
        float* orow = out + ((size_t)b * NS + row) * ND + h * DH;
#pragma unroll
        for (int nt = 0; nt < 8; nt++) {
            float2 o = make_float2(oacc[nt][hi * 2 + 0] * inv,
                                   oacc[nt][hi * 2 + 1] * inv);
            *(float2*)&orow[nt * 8 + cq] = o;
        }
    }
}

extern "C" void kernel_launch(void* const* d_in, const int* in_sizes, int n_in,
                              void* d_out, int out_size) {
    const float* hs   = (const float*)d_in[0];  // [B,S,D]
    const float* mask = (const float*)d_in[1];  // [B,S]
    const float* w    = (const float*)d_in[2];  // [D,3D]
    const float* bias = (const float*)d_in[3];  // [3D]

    float* out = (float*)d_out;
    float* kout = out + (size_t)NB * NS * ND;        // present[0] = K
    float* vout = kout + (size_t)NB * NH * NS * DH;  // present[1] = V

    cudaFuncSetAttribute(qkv_hmma_kernel,
                         cudaFuncAttributeMaxDynamicSharedMemorySize, 2 * STAGE_B);
    cudaFuncSetAttribute(attn_hmma_kernel,
                         cudaFuncAttributeMaxDynamicSharedMemorySize, ATT_SMEM_B);

    // 1) bf16 hi/lo splits
    split_a_kernel<<<(MROWS * ND) / (256 * 4), 256>>>(hs);
    split_wt_kernel<<<dim3(N3 / 32, ND / 32), dim3(32, 8)>>>(w);
    // 2) HMMA QKV GEMM (+ bias, bf16 Q/K/V^T emission, fp32 present)
    qkv_hmma_kernel<<<dim3(N3 / 128, MROWS / 128), 256, 2 * STAGE_B>>>(
        bias, kout, vout);
    // 3) HMMA flash attention
    attn_hmma_kernel<<<dim3(NS / 64, NH, NB), 128, ATT_SMEM_B>>>(mask, out);
}